// round 1
// baseline (speedup 1.0000x reference)
#include <cuda_runtime.h>
#include <math.h>
#include <float.h>

#define B_Q   64
#define DIM   768
#define N_MAX 500000
#define TOPK  10

// Scratch (static device allocations are allowed; no cudaMalloc anywhere).
__device__ float g_qn[B_Q * DIM];                    // normalized queries, 192 KB
__device__ float g_sims[(size_t)B_Q * N_MAX];        // similarity matrix, 128 MB

// ---------------------------------------------------------------------------
// Kernel 1: L2-normalize the 64 query vectors. One block per query.
// ---------------------------------------------------------------------------
__global__ void normalize_q(const float* __restrict__ q) {
    __shared__ float red[256];
    const int b = blockIdx.x;
    const float* row = q + (size_t)b * DIM;
    float ss = 0.f;
    for (int i = threadIdx.x; i < DIM; i += 256) {
        float v = row[i];
        ss += v * v;
    }
    red[threadIdx.x] = ss;
    __syncthreads();
    for (int s = 128; s > 0; s >>= 1) {
        if (threadIdx.x < s) red[threadIdx.x] += red[threadIdx.x + s];
        __syncthreads();
    }
    const float inv = 1.0f / fmaxf(sqrtf(red[0]), 1e-12f);
    for (int i = threadIdx.x; i < DIM; i += 256)
        g_qn[b * DIM + i] = row[i] * inv;
}

// ---------------------------------------------------------------------------
// Kernel 2: fused GEMM + db-row-norm.
//   CTA tile: 64 queries x 128 db rows, K chunked by 16.
//   Thread map: tx = tid%16 (4 queries each), ty = tid/16 (8 rows each).
//   Also accumulates per-row squared norms from the smem tile, normalizes
//   in the epilogue, writes sims[q][row] to g_sims.
// ---------------------------------------------------------------------------
__global__ __launch_bounds__(256, 2) void gemm_sims(const float* __restrict__ db,
                                                    int N) {
    __shared__ float q_s[16][64];
    __shared__ float db_s[16][128];
    __shared__ float norm_s[128];

    const int tid = threadIdx.x;
    const int tx = tid & 15;          // query group (4 queries)
    const int ty = tid >> 4;          // row group (8 rows)
    const int r0 = blockIdx.x * 128;

    float acc[4][8];
#pragma unroll
    for (int i = 0; i < 4; i++)
#pragma unroll
        for (int j = 0; j < 8; j++) acc[i][j] = 0.f;

    float nacc = 0.f;  // threads < 128 accumulate norm of row r0+tid

    for (int k0 = 0; k0 < DIM; k0 += 16) {
        // load query chunk (64 q x 16 k) transposed into q_s[k][q]
#pragma unroll
        for (int i = 0; i < 4; i++) {
            int idx = tid + i * 256;
            int qq = idx >> 4;
            int kk = idx & 15;
            q_s[kk][qq] = g_qn[qq * DIM + k0 + kk];
        }
        // load db chunk (128 rows x 16 k) transposed into db_s[k][r]
#pragma unroll
        for (int i = 0; i < 2; i++) {
            int idx = tid + i * 256;
            int rr = idx >> 2;
            int kq = (idx & 3) * 4;
            int gr = r0 + rr;
            float4 v = make_float4(0.f, 0.f, 0.f, 0.f);
            if (gr < N)
                v = *reinterpret_cast<const float4*>(db + (size_t)gr * DIM + k0 + kq);
            db_s[kq + 0][rr] = v.x;
            db_s[kq + 1][rr] = v.y;
            db_s[kq + 2][rr] = v.z;
            db_s[kq + 3][rr] = v.w;
        }
        __syncthreads();

        // per-row squared-norm accumulation (threads 0..127 own one row each)
        if (tid < 128) {
#pragma unroll
            for (int k = 0; k < 16; k++) {
                float v = db_s[k][tid];
                nacc += v * v;
            }
        }

        // main FMA loop: 32 FMA per k-step per thread
#pragma unroll
        for (int k = 0; k < 16; k++) {
            float4 qf = *reinterpret_cast<const float4*>(&q_s[k][tx * 4]);
            float4 d0 = *reinterpret_cast<const float4*>(&db_s[k][ty * 8]);
            float4 d1 = *reinterpret_cast<const float4*>(&db_s[k][ty * 8 + 4]);
            float qa[4] = {qf.x, qf.y, qf.z, qf.w};
            float da[8] = {d0.x, d0.y, d0.z, d0.w, d1.x, d1.y, d1.z, d1.w};
#pragma unroll
            for (int i = 0; i < 4; i++)
#pragma unroll
                for (int j = 0; j < 8; j++) acc[i][j] = fmaf(qa[i], da[j], acc[i][j]);
        }
        __syncthreads();
    }

    if (tid < 128) norm_s[tid] = nacc;
    __syncthreads();

    // epilogue: apply 1/max(||row||, 1e-12), write sims[q][row]
    float inv[8];
#pragma unroll
    for (int j = 0; j < 8; j++)
        inv[j] = 1.0f / fmaxf(sqrtf(norm_s[ty * 8 + j]), 1e-12f);

#pragma unroll
    for (int i = 0; i < 4; i++) {
        const int qq = tx * 4 + i;
#pragma unroll
        for (int j = 0; j < 8; j++) {
            int r = r0 + ty * 8 + j;
            if (r < N) g_sims[(size_t)qq * N + r] = acc[i][j] * inv[j];
        }
    }
}

// ---------------------------------------------------------------------------
// Kernel 3: top-10 per query. One block (512 threads) per query.
//   Per-thread register top-10 -> warp merge (lane 0) -> block merge (thread 0).
//   Tie-break: equal score -> lower index (matches jax.lax.top_k).
// ---------------------------------------------------------------------------
__device__ __forceinline__ bool better(float v, int vi, float s, int si) {
    return (v > s) || (v == s && vi < si);
}

__global__ void topk_kernel(float* __restrict__ out, int N, int Bq) {
    __shared__ float s_sc[512 * TOPK];   // 20 KB
    __shared__ int   s_id[512 * TOPK];   // 20 KB
    __shared__ float w_sc[16 * TOPK];
    __shared__ int   w_id[16 * TOPK];

    const int q    = blockIdx.x;
    const int tid  = threadIdx.x;
    const int lane = tid & 31;
    const int wid  = tid >> 5;
    const float* sims = g_sims + (size_t)q * N;

    float s[TOPK];
    int   id[TOPK];
#pragma unroll
    for (int t = 0; t < TOPK; t++) { s[t] = -FLT_MAX; id[t] = 0x7fffffff; }

    for (int i = tid; i < N; i += 512) {
        float v = sims[i];
        if (v > s[TOPK - 1] || (v == s[TOPK - 1] && i < id[TOPK - 1])) {
            float cv = v; int ci = i;
#pragma unroll
            for (int t = 0; t < TOPK; t++) {
                if (better(cv, ci, s[t], id[t])) {
                    float ts = s[t]; int ti = id[t];
                    s[t] = cv; id[t] = ci;
                    cv = ts; ci = ti;
                }
            }
        }
    }

#pragma unroll
    for (int t = 0; t < TOPK; t++) {
        s_sc[tid * TOPK + t] = s[t];
        s_id[tid * TOPK + t] = id[t];
    }
    __syncthreads();

    // warp-level merge by lane 0 of each warp (320 candidates)
    if (lane == 0) {
        float ws[TOPK]; int wi[TOPK];
#pragma unroll
        for (int t = 0; t < TOPK; t++) { ws[t] = -FLT_MAX; wi[t] = 0x7fffffff; }
        const int base = wid * 32 * TOPK;
        for (int c = 0; c < 32 * TOPK; c++) {
            float v = s_sc[base + c];
            int   vi = s_id[base + c];
            if (v > ws[TOPK - 1] || (v == ws[TOPK - 1] && vi < wi[TOPK - 1])) {
                float cv = v; int ci = vi;
#pragma unroll
                for (int t = 0; t < TOPK; t++) {
                    if (better(cv, ci, ws[t], wi[t])) {
                        float ts = ws[t]; int ti = wi[t];
                        ws[t] = cv; wi[t] = ci;
                        cv = ts; ci = ti;
                    }
                }
            }
        }
#pragma unroll
        for (int t = 0; t < TOPK; t++) {
            w_sc[wid * TOPK + t] = ws[t];
            w_id[wid * TOPK + t] = wi[t];
        }
    }
    __syncthreads();

    // final merge of 16 warp-results by thread 0
    if (tid == 0) {
        float fs[TOPK]; int fi[TOPK];
#pragma unroll
        for (int t = 0; t < TOPK; t++) { fs[t] = -FLT_MAX; fi[t] = 0x7fffffff; }
        for (int c = 0; c < 16 * TOPK; c++) {
            float v = w_sc[c];
            int   vi = w_id[c];
            if (v > fs[TOPK - 1] || (v == fs[TOPK - 1] && vi < fi[TOPK - 1])) {
                float cv = v; int ci = vi;
#pragma unroll
                for (int t = 0; t < TOPK; t++) {
                    if (better(cv, ci, fs[t], fi[t])) {
                        float ts = fs[t]; int ti = fi[t];
                        fs[t] = cv; fi[t] = ci;
                        cv = ts; ci = ti;
                    }
                }
            }
        }
        // output: scores [B,10] then indices [B,10] (as float), flattened.
#pragma unroll
        for (int t = 0; t < TOPK; t++) {
            out[q * TOPK + t]              = fs[t];
            out[Bq * TOPK + q * TOPK + t]  = (float)fi[t];
        }
    }
}

// ---------------------------------------------------------------------------
extern "C" void kernel_launch(void* const* d_in, const int* in_sizes, int n_in,
                              void* d_out, int out_size) {
    const float* query = (const float*)d_in[0];
    const float* db    = (const float*)d_in[1];

    int Bq = in_sizes[0] / DIM;            // expect 64
    int N  = in_sizes[1] / DIM;            // expect 500000
    if (Bq > B_Q) Bq = B_Q;
    if (N > N_MAX) N = N_MAX;

    float* out = (float*)d_out;

    normalize_q<<<Bq, 256>>>(query);
    int nblk = (N + 127) / 128;
    gemm_sims<<<nblk, 256>>>(db, N);
    topk_kernel<<<Bq, 512>>>(out, N, Bq);
    (void)n_in; (void)out_size;
}

// round 4
// speedup vs baseline: 1.8363x; 1.8363x over previous
#include <cuda_runtime.h>
#include <math.h>
#include <float.h>

#define DIM     768
#define B_Q     64
#define N_MAX   500000
#define TOPK    10
#define K_CAND  32          // candidates per query for exact rescoring

#define BLK_M   256         // db rows per CTA
#define BLK_K   32          // K chunk
#define PADS    36          // smem row stride (floats) -> conflict-free frags
#define NPARTS  4           // top-k split factor per query

#define TPB_TOPK 256        // threads per topk_part block (reg-file safe)

// ---- static device scratch (no cudaMalloc allowed) ----
__device__ float g_qn[B_Q * DIM];                 // normalized queries
__device__ float g_sims[(size_t)B_Q * N_MAX];     // tf32 similarity matrix
__device__ float g_part_sc[B_Q * NPARTS * K_CAND];
__device__ int   g_part_id[B_Q * NPARTS * K_CAND];
__device__ int   g_cand_id[B_Q * K_CAND];
__device__ float g_exact[B_Q * K_CAND];

// ---------------------------------------------------------------------------
// Kernel 1: L2-normalize queries. One block per query.
// ---------------------------------------------------------------------------
__global__ __launch_bounds__(256) void normalize_q(const float* __restrict__ q) {
    __shared__ float red[256];
    const int b = blockIdx.x;
    const float* row = q + (size_t)b * DIM;
    float ss = 0.f;
    for (int i = threadIdx.x; i < DIM; i += 256) {
        float v = row[i];
        ss += v * v;
    }
    red[threadIdx.x] = ss;
    __syncthreads();
    for (int s = 128; s > 0; s >>= 1) {
        if (threadIdx.x < s) red[threadIdx.x] += red[threadIdx.x + s];
        __syncthreads();
    }
    const float inv = 1.0f / fmaxf(sqrtf(red[0]), 1e-12f);
    for (int i = threadIdx.x; i < DIM; i += 256)
        g_qn[b * DIM + i] = row[i] * inv;
}

// ---------------------------------------------------------------------------
// tf32 helpers
// ---------------------------------------------------------------------------
__device__ __forceinline__ unsigned f2tf(float f) {
    unsigned u;
    asm("cvt.rna.tf32.f32 %0, %1;" : "=r"(u) : "f"(f));
    return u;
}

__device__ __forceinline__ void cp16(float* dst_smem, const float* src) {
    unsigned d = (unsigned)__cvta_generic_to_shared(dst_smem);
    asm volatile("cp.async.cg.shared.global [%0], [%1], 16;" :: "r"(d), "l"(src));
}

// ---------------------------------------------------------------------------
// Kernel 2: tensor-core GEMM (tf32) fused with db row-norm.
//   CTA: 256 db rows x 64 queries. 8 warps, warp tile m32 x n64.
//   Double-buffered cp.async on K chunks of 32.
// ---------------------------------------------------------------------------
__global__ __launch_bounds__(256, 2) void gemm_tc(const float* __restrict__ db,
                                                  int N) {
    extern __shared__ float sm[];
    float* db_s   = sm;                              // [2][256][36]
    float* q_s    = sm + 2 * BLK_M * PADS;           // [2][64][36]
    float* norm_s = q_s + 2 * 64 * PADS;             // [256]

    const int tid  = threadIdx.x;
    const int lane = tid & 31;
    const int warp = tid >> 5;
    const int gid  = lane >> 2;
    const int tig  = lane & 3;
    const int r0   = blockIdx.x * BLK_M;

    float acc[2][8][4];
#pragma unroll
    for (int mt = 0; mt < 2; mt++)
#pragma unroll
        for (int nt = 0; nt < 8; nt++)
#pragma unroll
            for (int k = 0; k < 4; k++) acc[mt][nt][k] = 0.f;

    float nacc = 0.f;
    const int NC = DIM / BLK_K;  // 24

    auto issue = [&](int c) {
        const int s  = c & 1;
        const int k0 = c * BLK_K;
        float* dbd = db_s + s * BLK_M * PADS;
        float* qd  = q_s + s * 64 * PADS;
#pragma unroll
        for (int i = 0; i < 8; i++) {
            int idx = tid + i * 256;
            int row = idx >> 3;
            int jj  = idx & 7;
            int gr  = r0 + row;
            if (gr >= N) gr = N - 1;
            cp16(dbd + row * PADS + jj * 4, db + (size_t)gr * DIM + k0 + jj * 4);
        }
#pragma unroll
        for (int i = 0; i < 2; i++) {
            int idx = tid + i * 256;
            int row = idx >> 3;
            int jj  = idx & 7;
            cp16(qd + row * PADS + jj * 4, g_qn + row * DIM + k0 + jj * 4);
        }
        asm volatile("cp.async.commit_group;");
    };

    issue(0);

    for (int c = 0; c < NC; c++) {
        const int s = c & 1;
        if (c + 1 < NC) {
            issue(c + 1);
            asm volatile("cp.async.wait_group 1;");
        } else {
            asm volatile("cp.async.wait_group 0;");
        }
        __syncthreads();

        {
            const float* rowp = db_s + s * BLK_M * PADS + tid * PADS;
#pragma unroll
            for (int jj = 0; jj < 8; jj++) {
                float4 v = *reinterpret_cast<const float4*>(rowp + jj * 4);
                nacc += v.x * v.x + v.y * v.y + v.z * v.z + v.w * v.w;
            }
        }

        const float* dbb = db_s + s * BLK_M * PADS + (warp * 32) * PADS;
        const float* qb  = q_s + s * 64 * PADS;

#pragma unroll
        for (int ks = 0; ks < BLK_K; ks += 8) {
            unsigned a[2][4], b[8][2];
#pragma unroll
            for (int mt = 0; mt < 2; mt++) {
                const float* ap = dbb + (mt * 16 + gid) * PADS + ks + tig;
                a[mt][0] = f2tf(ap[0]);
                a[mt][1] = f2tf(ap[8 * PADS]);
                a[mt][2] = f2tf(ap[4]);
                a[mt][3] = f2tf(ap[8 * PADS + 4]);
            }
#pragma unroll
            for (int nt = 0; nt < 8; nt++) {
                const float* bp = qb + (nt * 8 + gid) * PADS + ks + tig;
                b[nt][0] = f2tf(bp[0]);
                b[nt][1] = f2tf(bp[4]);
            }
#pragma unroll
            for (int mt = 0; mt < 2; mt++)
#pragma unroll
                for (int nt = 0; nt < 8; nt++) {
                    float* c4 = acc[mt][nt];
                    asm volatile(
                        "mma.sync.aligned.m16n8k8.row.col.f32.tf32.tf32.f32 "
                        "{%0,%1,%2,%3},{%4,%5,%6,%7},{%8,%9},{%0,%1,%2,%3};"
                        : "+f"(c4[0]), "+f"(c4[1]), "+f"(c4[2]), "+f"(c4[3])
                        : "r"(a[mt][0]), "r"(a[mt][1]), "r"(a[mt][2]), "r"(a[mt][3]),
                          "r"(b[nt][0]), "r"(b[nt][1]));
                }
        }
        __syncthreads();
    }

    norm_s[tid] = nacc;
    __syncthreads();

#pragma unroll
    for (int mt = 0; mt < 2; mt++) {
        const int lr0 = warp * 32 + mt * 16 + gid;
        const float inv0 = 1.f / fmaxf(sqrtf(norm_s[lr0]), 1e-12f);
        const float inv1 = 1.f / fmaxf(sqrtf(norm_s[lr0 + 8]), 1e-12f);
        const int gr0 = r0 + lr0;
#pragma unroll
        for (int nt = 0; nt < 8; nt++) {
            const int q = nt * 8 + 2 * tig;
            if (gr0 < N) {
                g_sims[(size_t)q * N + gr0]       = acc[mt][nt][0] * inv0;
                g_sims[(size_t)(q + 1) * N + gr0] = acc[mt][nt][1] * inv0;
            }
            if (gr0 + 8 < N) {
                g_sims[(size_t)q * N + gr0 + 8]       = acc[mt][nt][2] * inv1;
                g_sims[(size_t)(q + 1) * N + gr0 + 8] = acc[mt][nt][3] * inv1;
            }
        }
    }
}

// ---------------------------------------------------------------------------
// Top-k machinery. Tie-break: equal score -> lower index.
// ---------------------------------------------------------------------------
__device__ __forceinline__ bool better(float v, int vi, float s, int si) {
    return (v > s) || (v == s && vi < si);
}

template <int D>
__device__ __forceinline__ void insertD(float v, int vi, float* s, int* id) {
    if (v > s[D - 1] || (v == s[D - 1] && vi < id[D - 1])) {
        float cv = v; int ci = vi;
#pragma unroll
        for (int t = 0; t < D; t++) {
            if (better(cv, ci, s[t], id[t])) {
                float ts = s[t]; int ti = id[t];
                s[t] = cv; id[t] = ci;
                cv = ts; ci = ti;
            }
        }
    }
}

// Partial candidate selection: grid (Bq, NPARTS), 256 threads (reg-safe).
// Per-thread top-10 -> warp top-32 (lane 0) -> block top-32 (thread 0).
__global__ __launch_bounds__(TPB_TOPK) void topk_part(int N) {
    __shared__ float s_sc[TPB_TOPK * TOPK];   // 10 KB
    __shared__ int   s_id[TPB_TOPK * TOPK];   // 10 KB
    __shared__ float w_sc[8 * K_CAND];
    __shared__ int   w_id[8 * K_CAND];

    const int q    = blockIdx.x;
    const int p    = blockIdx.y;
    const int tid  = threadIdx.x;
    const int lane = tid & 31;
    const int wid  = tid >> 5;

    const int chunk = (((N + NPARTS - 1) / NPARTS) + 3) & ~3;
    const int start = p * chunk;
    int end = start + chunk;
    if (end > N) end = N;

    const float* sims = g_sims + (size_t)q * N;

    float s[TOPK];
    int   id[TOPK];
#pragma unroll
    for (int t = 0; t < TOPK; t++) { s[t] = -FLT_MAX; id[t] = 0x7fffffff; }

    if (start < end) {
        const int nf4 = (end - start) >> 2;
        const float4* sims4 = reinterpret_cast<const float4*>(sims + start);
        for (int j = tid; j < nf4; j += TPB_TOPK) {
            float4 v = sims4[j];
            int base = start + j * 4;
            insertD<TOPK>(v.x, base + 0, s, id);
            insertD<TOPK>(v.y, base + 1, s, id);
            insertD<TOPK>(v.z, base + 2, s, id);
            insertD<TOPK>(v.w, base + 3, s, id);
        }
        for (int i = start + nf4 * 4 + tid; i < end; i += TPB_TOPK)
            insertD<TOPK>(sims[i], i, s, id);
    }

#pragma unroll
    for (int t = 0; t < TOPK; t++) {
        s_sc[tid * TOPK + t] = s[t];
        s_id[tid * TOPK + t] = id[t];
    }
    __syncthreads();

    if (lane == 0) {
        float ws[K_CAND]; int wi[K_CAND];
#pragma unroll
        for (int t = 0; t < K_CAND; t++) { ws[t] = -FLT_MAX; wi[t] = 0x7fffffff; }
        const int base = wid * 32 * TOPK;
        for (int c = 0; c < 32 * TOPK; c++)
            insertD<K_CAND>(s_sc[base + c], s_id[base + c], ws, wi);
#pragma unroll
        for (int t = 0; t < K_CAND; t++) {
            w_sc[wid * K_CAND + t] = ws[t];
            w_id[wid * K_CAND + t] = wi[t];
        }
    }
    __syncthreads();

    if (tid == 0) {
        float fs[K_CAND]; int fi[K_CAND];
#pragma unroll
        for (int t = 0; t < K_CAND; t++) { fs[t] = -FLT_MAX; fi[t] = 0x7fffffff; }
        for (int c = 0; c < 8 * K_CAND; c++)
            insertD<K_CAND>(w_sc[c], w_id[c], fs, fi);
#pragma unroll
        for (int t = 0; t < K_CAND; t++) {
            g_part_sc[(q * NPARTS + p) * K_CAND + t] = fs[t];
            g_part_id[(q * NPARTS + p) * K_CAND + t] = fi[t];
        }
    }
}

// Merge the NPARTS partial candidate lists -> K_CAND candidates per query.
__global__ __launch_bounds__(32) void cand_merge() {
    const int q = blockIdx.x;
    if (threadIdx.x != 0) return;
    float fs[K_CAND]; int fi[K_CAND];
#pragma unroll
    for (int t = 0; t < K_CAND; t++) { fs[t] = -FLT_MAX; fi[t] = 0x7fffffff; }
    for (int c = 0; c < NPARTS * K_CAND; c++)
        insertD<K_CAND>(g_part_sc[q * NPARTS * K_CAND + c],
                        g_part_id[q * NPARTS * K_CAND + c], fs, fi);
#pragma unroll
    for (int t = 0; t < K_CAND; t++)
        g_cand_id[q * K_CAND + t] = fi[t];
}

// Exact fp32 rescore: one block per (query, candidate).
__global__ __launch_bounds__(256) void rescore(const float* __restrict__ db, int N) {
    __shared__ float red_dot[256];
    __shared__ float red_nn[256];
    const int q = blockIdx.x;
    const int c = blockIdx.y;
    const int tid = threadIdx.x;
    const int idx = g_cand_id[q * K_CAND + c];

    float dot = 0.f, nn = 0.f;
    if (idx >= 0 && idx < N) {
        const float* row = db + (size_t)idx * DIM;
        const float* qp  = g_qn + q * DIM;
        for (int i = tid; i < DIM; i += 256) {
            float d = row[i];
            dot += qp[i] * d;
            nn  += d * d;
        }
    }
    red_dot[tid] = dot;
    red_nn[tid]  = nn;
    __syncthreads();
    for (int s = 128; s > 0; s >>= 1) {
        if (tid < s) {
            red_dot[tid] += red_dot[tid + s];
            red_nn[tid]  += red_nn[tid + s];
        }
        __syncthreads();
    }
    if (tid == 0) {
        float sim = (idx >= 0 && idx < N)
                        ? red_dot[0] / fmaxf(sqrtf(red_nn[0]), 1e-12f)
                        : -FLT_MAX;
        g_exact[q * K_CAND + c] = sim;
    }
}

// Final top-10 over the exact scores.
__global__ __launch_bounds__(32) void topk_final(float* __restrict__ out, int Bq) {
    const int q = blockIdx.x;
    if (threadIdx.x != 0) return;
    float fs[TOPK]; int fi[TOPK];
#pragma unroll
    for (int t = 0; t < TOPK; t++) { fs[t] = -FLT_MAX; fi[t] = 0x7fffffff; }
    for (int c = 0; c < K_CAND; c++)
        insertD<TOPK>(g_exact[q * K_CAND + c], g_cand_id[q * K_CAND + c], fs, fi);
#pragma unroll
    for (int t = 0; t < TOPK; t++) {
        out[q * TOPK + t]             = fs[t];
        out[Bq * TOPK + q * TOPK + t] = (float)fi[t];
    }
}

// ---------------------------------------------------------------------------
extern "C" void kernel_launch(void* const* d_in, const int* in_sizes, int n_in,
                              void* d_out, int out_size) {
    const float* query = (const float*)d_in[0];
    const float* db    = (const float*)d_in[1];

    int Bq = in_sizes[0] / DIM;
    int N  = in_sizes[1] / DIM;
    if (Bq > B_Q) Bq = B_Q;
    if (N > N_MAX) N = N_MAX;

    float* out = (float*)d_out;

    static bool attr_set = false;
    const int smem_bytes = (2 * BLK_M * PADS + 2 * 64 * PADS + 256) * 4;
    if (!attr_set) {
        cudaFuncSetAttribute(gemm_tc, cudaFuncAttributeMaxDynamicSharedMemorySize,
                             smem_bytes);
        attr_set = true;
    }

    normalize_q<<<Bq, 256>>>(query);
    const int nblk = (N + BLK_M - 1) / BLK_M;
    gemm_tc<<<nblk, 256, smem_bytes>>>(db, N);
    dim3 pgrid(Bq, NPARTS);
    topk_part<<<pgrid, TPB_TOPK>>>(N);
    cand_merge<<<Bq, 32>>>();
    dim3 rgrid(Bq, K_CAND);
    rescore<<<rgrid, 256>>>(db, N);
    topk_final<<<Bq, 32>>>(out, Bq);
    (void)n_in; (void)out_size;
}

// round 5
// speedup vs baseline: 2.0086x; 1.0939x over previous
#include <cuda_runtime.h>
#include <cuda_bf16.h>
#include <math.h>
#include <float.h>

#define DIM     768
#define B_Q     64
#define N_MAX   500000
#define TOPK    10
#define K_CAND  32          // candidates per query for exact rescoring

#define BLK_M   256         // db rows per CTA
#define BLK_K   32          // K chunk
#define STF     36          // fp32 stage row stride (floats), 16B-aligned, conflict-free float4
#define PADB    40          // bf16 tile row stride (elements) -> conflict-free frags
#define NPARTS  4           // top-k split factor per query

#define TPB_TOPK 256

// ---- static device scratch (no cudaMalloc anywhere) ----
__device__ float          g_qn[B_Q * DIM];        // normalized queries (fp32, for rescore)
__device__ __nv_bfloat16  g_qn_bf[B_Q * DIM];     // normalized queries (bf16, for GEMM)
__device__ float          g_sims[(size_t)B_Q * N_MAX];
__device__ float          g_part_sc[B_Q * NPARTS * K_CAND];
__device__ int            g_part_id[B_Q * NPARTS * K_CAND];
__device__ int            g_cand_id[B_Q * K_CAND];
__device__ float          g_exact[B_Q * K_CAND];

// smem layout for gemm (bytes)
#define SM_STAGE   0                       // fp32 stage: [2][256][STF]  = 73728 B
#define SM_DBBF    (2 * BLK_M * STF * 4)   // bf16 db tile: [256][PADB]  = 20480 B
#define SM_QBF     (SM_DBBF + BLK_M * PADB * 2)          // [2][64][PADB] = 10240 B
#define SM_NORM    (SM_QBF + 2 * 64 * PADB * 2)          // [256] floats  = 1024 B
#define SM_TOTAL   (SM_NORM + BLK_M * 4)                 // 105472 B

// ---------------------------------------------------------------------------
// Kernel 1: L2-normalize queries; write fp32 + bf16 copies.
// ---------------------------------------------------------------------------
__global__ __launch_bounds__(256) void normalize_q(const float* __restrict__ q) {
    __shared__ float red[256];
    const int b = blockIdx.x;
    const float* row = q + (size_t)b * DIM;
    float ss = 0.f;
    for (int i = threadIdx.x; i < DIM; i += 256) {
        float v = row[i];
        ss += v * v;
    }
    red[threadIdx.x] = ss;
    __syncthreads();
    for (int s = 128; s > 0; s >>= 1) {
        if (threadIdx.x < s) red[threadIdx.x] += red[threadIdx.x + s];
        __syncthreads();
    }
    const float inv = 1.0f / fmaxf(sqrtf(red[0]), 1e-12f);
    for (int i = threadIdx.x; i < DIM; i += 256) {
        float v = row[i] * inv;
        g_qn[b * DIM + i]    = v;
        g_qn_bf[b * DIM + i] = __float2bfloat16_rn(v);
    }
}

__device__ __forceinline__ void cp16(void* dst_smem, const void* src) {
    unsigned d = (unsigned)__cvta_generic_to_shared(dst_smem);
    asm volatile("cp.async.cg.shared.global [%0], [%1], 16;" :: "r"(d), "l"(src));
}

// ---------------------------------------------------------------------------
// Kernel 2: bf16 tensor-core GEMM fused with db row-norm.
//   CTA: 256 db rows x 64 queries. 8 warps, warp tile m32 x n64.
//   fp32 chunk staged via cp.async (double-buffered) -> converted once to a
//   bf16 tile (norm fused into conversion) -> mma.m16n8k16.bf16.
// ---------------------------------------------------------------------------
__global__ __launch_bounds__(256, 2) void gemm_tc(const float* __restrict__ db,
                                                  int N) {
    extern __shared__ char smc[];
    float*          stage  = reinterpret_cast<float*>(smc + SM_STAGE);
    __nv_bfloat16*  db_bf  = reinterpret_cast<__nv_bfloat16*>(smc + SM_DBBF);
    __nv_bfloat16*  q_bf   = reinterpret_cast<__nv_bfloat16*>(smc + SM_QBF);
    float*          norm_s = reinterpret_cast<float*>(smc + SM_NORM);

    const int tid  = threadIdx.x;
    const int lane = tid & 31;
    const int warp = tid >> 5;
    const int gid  = lane >> 2;
    const int tig  = lane & 3;
    const int r0   = blockIdx.x * BLK_M;

    float acc[2][8][4];
#pragma unroll
    for (int mt = 0; mt < 2; mt++)
#pragma unroll
        for (int nt = 0; nt < 8; nt++)
#pragma unroll
            for (int k = 0; k < 4; k++) acc[mt][nt][k] = 0.f;

    float nacc = 0.f;
    const int NC = DIM / BLK_K;  // 24

    auto issue = [&](int c) {
        const int s  = c & 1;
        const int k0 = c * BLK_K;
        float* st = stage + s * BLK_M * STF;
        // db: 2048 x 16B segments, 8 per thread
#pragma unroll
        for (int i = 0; i < 8; i++) {
            int idx = tid + i * 256;
            int row = idx >> 3;
            int jj  = idx & 7;
            int gr  = r0 + row;
            if (gr >= N) gr = N - 1;
            cp16(st + row * STF + jj * 4, db + (size_t)gr * DIM + k0 + jj * 4);
        }
        // q (bf16 source): 64 rows x 64B = 256 x 16B segments, 1 per thread
        {
            int row = tid >> 2;
            int seg = tid & 3;
            cp16(q_bf + s * 64 * PADB + row * PADB + seg * 8,
                 g_qn_bf + row * DIM + k0 + seg * 8);
        }
        asm volatile("cp.async.commit_group;");
    };

    issue(0);

    for (int c = 0; c < NC; c++) {
        const int s = c & 1;
        if (c + 1 < NC) {
            issue(c + 1);
            asm volatile("cp.async.wait_group 1;");
        } else {
            asm volatile("cp.async.wait_group 0;");
        }
        __syncthreads();   // stage[s]+q_bf[s] ready; db_bf free (prev mma done)

        // convert fp32 stage -> bf16 tile, fuse row-norm. Thread owns row tid.
        {
            const float4* rp =
                reinterpret_cast<const float4*>(stage + s * BLK_M * STF + tid * STF);
            __nv_bfloat162* wp =
                reinterpret_cast<__nv_bfloat162*>(db_bf + tid * PADB);
#pragma unroll
            for (int j = 0; j < 8; j++) {
                float4 v = rp[j];
                nacc += v.x * v.x + v.y * v.y + v.z * v.z + v.w * v.w;
                wp[2 * j]     = __float22bfloat162_rn(make_float2(v.x, v.y));
                wp[2 * j + 1] = __float22bfloat162_rn(make_float2(v.z, v.w));
            }
        }
        __syncthreads();   // db_bf ready

        const __nv_bfloat16* dbb = db_bf + (warp * 32) * PADB;
        const __nv_bfloat16* qb  = q_bf + s * 64 * PADB;

#pragma unroll
        for (int ks = 0; ks < BLK_K; ks += 16) {
            unsigned a[2][4], b[8][2];
#pragma unroll
            for (int mt = 0; mt < 2; mt++) {
                const __nv_bfloat16* ap = dbb + (mt * 16 + gid) * PADB + ks + 2 * tig;
                a[mt][0] = *reinterpret_cast<const unsigned*>(ap);
                a[mt][1] = *reinterpret_cast<const unsigned*>(ap + 8 * PADB);
                a[mt][2] = *reinterpret_cast<const unsigned*>(ap + 8);
                a[mt][3] = *reinterpret_cast<const unsigned*>(ap + 8 * PADB + 8);
            }
#pragma unroll
            for (int nt = 0; nt < 8; nt++) {
                const __nv_bfloat16* bp = qb + (nt * 8 + gid) * PADB + ks + 2 * tig;
                b[nt][0] = *reinterpret_cast<const unsigned*>(bp);
                b[nt][1] = *reinterpret_cast<const unsigned*>(bp + 8);
            }
#pragma unroll
            for (int mt = 0; mt < 2; mt++)
#pragma unroll
                for (int nt = 0; nt < 8; nt++) {
                    float* c4 = acc[mt][nt];
                    asm volatile(
                        "mma.sync.aligned.m16n8k16.row.col.f32.bf16.bf16.f32 "
                        "{%0,%1,%2,%3},{%4,%5,%6,%7},{%8,%9},{%0,%1,%2,%3};"
                        : "+f"(c4[0]), "+f"(c4[1]), "+f"(c4[2]), "+f"(c4[3])
                        : "r"(a[mt][0]), "r"(a[mt][1]), "r"(a[mt][2]), "r"(a[mt][3]),
                          "r"(b[nt][0]), "r"(b[nt][1]));
                }
        }
        __syncthreads();   // mma done before next convert overwrites db_bf
    }

    norm_s[tid] = nacc;
    __syncthreads();

#pragma unroll
    for (int mt = 0; mt < 2; mt++) {
        const int lr0 = warp * 32 + mt * 16 + gid;
        const float inv0 = 1.f / fmaxf(sqrtf(norm_s[lr0]), 1e-12f);
        const float inv1 = 1.f / fmaxf(sqrtf(norm_s[lr0 + 8]), 1e-12f);
        const int gr0 = r0 + lr0;
#pragma unroll
        for (int nt = 0; nt < 8; nt++) {
            const int q = nt * 8 + 2 * tig;
            if (gr0 < N) {
                g_sims[(size_t)q * N + gr0]       = acc[mt][nt][0] * inv0;
                g_sims[(size_t)(q + 1) * N + gr0] = acc[mt][nt][1] * inv0;
            }
            if (gr0 + 8 < N) {
                g_sims[(size_t)q * N + gr0 + 8]       = acc[mt][nt][2] * inv1;
                g_sims[(size_t)(q + 1) * N + gr0 + 8] = acc[mt][nt][3] * inv1;
            }
        }
    }
}

// ---------------------------------------------------------------------------
// Top-k machinery. Tie-break: equal score -> lower index.
// ---------------------------------------------------------------------------
__device__ __forceinline__ bool better(float v, int vi, float s, int si) {
    return (v > s) || (v == s && vi < si);
}

template <int D>
__device__ __forceinline__ void insertD(float v, int vi, float* s, int* id) {
    if (v > s[D - 1] || (v == s[D - 1] && vi < id[D - 1])) {
        float cv = v; int ci = vi;
#pragma unroll
        for (int t = 0; t < D; t++) {
            if (better(cv, ci, s[t], id[t])) {
                float ts = s[t]; int ti = id[t];
                s[t] = cv; id[t] = ci;
                cv = ts; ci = ti;
            }
        }
    }
}

// Partial candidate selection: grid (Bq, NPARTS), 256 threads.
__global__ __launch_bounds__(TPB_TOPK) void topk_part(int N) {
    __shared__ float s_sc[TPB_TOPK * TOPK];
    __shared__ int   s_id[TPB_TOPK * TOPK];
    __shared__ float w_sc[8 * K_CAND];
    __shared__ int   w_id[8 * K_CAND];

    const int q    = blockIdx.x;
    const int p    = blockIdx.y;
    const int tid  = threadIdx.x;
    const int lane = tid & 31;
    const int wid  = tid >> 5;

    const int chunk = (((N + NPARTS - 1) / NPARTS) + 3) & ~3;
    const int start = p * chunk;
    int end = start + chunk;
    if (end > N) end = N;

    const float* sims = g_sims + (size_t)q * N;

    float s[TOPK];
    int   id[TOPK];
#pragma unroll
    for (int t = 0; t < TOPK; t++) { s[t] = -FLT_MAX; id[t] = 0x7fffffff; }

    if (start < end) {
        const int nf4 = (end - start) >> 2;
        const float4* sims4 = reinterpret_cast<const float4*>(sims + start);
        for (int j = tid; j < nf4; j += TPB_TOPK) {
            float4 v = sims4[j];
            int base = start + j * 4;
            insertD<TOPK>(v.x, base + 0, s, id);
            insertD<TOPK>(v.y, base + 1, s, id);
            insertD<TOPK>(v.z, base + 2, s, id);
            insertD<TOPK>(v.w, base + 3, s, id);
        }
        for (int i = start + nf4 * 4 + tid; i < end; i += TPB_TOPK)
            insertD<TOPK>(sims[i], i, s, id);
    }

#pragma unroll
    for (int t = 0; t < TOPK; t++) {
        s_sc[tid * TOPK + t] = s[t];
        s_id[tid * TOPK + t] = id[t];
    }
    __syncthreads();

    if (lane == 0) {
        float ws[K_CAND]; int wi[K_CAND];
#pragma unroll
        for (int t = 0; t < K_CAND; t++) { ws[t] = -FLT_MAX; wi[t] = 0x7fffffff; }
        const int base = wid * 32 * TOPK;
        for (int c = 0; c < 32 * TOPK; c++)
            insertD<K_CAND>(s_sc[base + c], s_id[base + c], ws, wi);
#pragma unroll
        for (int t = 0; t < K_CAND; t++) {
            w_sc[wid * K_CAND + t] = ws[t];
            w_id[wid * K_CAND + t] = wi[t];
        }
    }
    __syncthreads();

    if (tid == 0) {
        float fs[K_CAND]; int fi[K_CAND];
#pragma unroll
        for (int t = 0; t < K_CAND; t++) { fs[t] = -FLT_MAX; fi[t] = 0x7fffffff; }
        for (int c = 0; c < 8 * K_CAND; c++)
            insertD<K_CAND>(w_sc[c], w_id[c], fs, fi);
#pragma unroll
        for (int t = 0; t < K_CAND; t++) {
            g_part_sc[(q * NPARTS + p) * K_CAND + t] = fs[t];
            g_part_id[(q * NPARTS + p) * K_CAND + t] = fi[t];
        }
    }
}

// Parallel rank-select merge: 128 candidates -> top K_CAND. One block/query.
__global__ __launch_bounds__(NPARTS * K_CAND) void cand_merge() {
    __shared__ float sc[NPARTS * K_CAND];
    __shared__ int   id[NPARTS * K_CAND];
    const int q = blockIdx.x;
    const int c = threadIdx.x;
    sc[c] = g_part_sc[q * NPARTS * K_CAND + c];
    id[c] = g_part_id[q * NPARTS * K_CAND + c];
    __syncthreads();
    const float mv = sc[c];
    const int   mi = id[c];
    int rank = 0;
    for (int j = 0; j < NPARTS * K_CAND; j++)
        rank += better(sc[j], id[j], mv, mi) ? 1 : 0;
    if (rank < K_CAND) g_cand_id[q * K_CAND + rank] = mi;
}

// Exact fp32 rescore: one block per (query, candidate).
__global__ __launch_bounds__(256) void rescore(const float* __restrict__ db, int N) {
    __shared__ float red_dot[256];
    __shared__ float red_nn[256];
    const int q = blockIdx.x;
    const int c = blockIdx.y;
    const int tid = threadIdx.x;
    const int idx = g_cand_id[q * K_CAND + c];

    float dot = 0.f, nn = 0.f;
    if (idx >= 0 && idx < N) {
        const float* row = db + (size_t)idx * DIM;
        const float* qp  = g_qn + q * DIM;
        for (int i = tid; i < DIM; i += 256) {
            float d = row[i];
            dot += qp[i] * d;
            nn  += d * d;
        }
    }
    red_dot[tid] = dot;
    red_nn[tid]  = nn;
    __syncthreads();
    for (int s = 128; s > 0; s >>= 1) {
        if (tid < s) {
            red_dot[tid] += red_dot[tid + s];
            red_nn[tid]  += red_nn[tid + s];
        }
        __syncthreads();
    }
    if (tid == 0) {
        float sim = (idx >= 0 && idx < N)
                        ? red_dot[0] / fmaxf(sqrtf(red_nn[0]), 1e-12f)
                        : -FLT_MAX;
        g_exact[q * K_CAND + c] = sim;
    }
}

// Parallel final top-10 over the exact scores (rank-select).
__global__ __launch_bounds__(K_CAND) void topk_final(float* __restrict__ out, int Bq) {
    __shared__ float sc[K_CAND];
    __shared__ int   id[K_CAND];
    const int q = blockIdx.x;
    const int c = threadIdx.x;
    sc[c] = g_exact[q * K_CAND + c];
    id[c] = g_cand_id[q * K_CAND + c];
    __syncthreads();
    const float mv = sc[c];
    const int   mi = id[c];
    int rank = 0;
    for (int j = 0; j < K_CAND; j++)
        rank += better(sc[j], id[j], mv, mi) ? 1 : 0;
    if (rank < TOPK) {
        out[q * TOPK + rank]             = mv;
        out[Bq * TOPK + q * TOPK + rank] = (float)mi;
    }
}

// ---------------------------------------------------------------------------
extern "C" void kernel_launch(void* const* d_in, const int* in_sizes, int n_in,
                              void* d_out, int out_size) {
    const float* query = (const float*)d_in[0];
    const float* db    = (const float*)d_in[1];

    int Bq = in_sizes[0] / DIM;
    int N  = in_sizes[1] / DIM;
    if (Bq > B_Q) Bq = B_Q;
    if (N > N_MAX) N = N_MAX;

    float* out = (float*)d_out;

    static bool attr_set = false;
    if (!attr_set) {
        cudaFuncSetAttribute(gemm_tc, cudaFuncAttributeMaxDynamicSharedMemorySize,
                             SM_TOTAL);
        attr_set = true;
    }

    normalize_q<<<Bq, 256>>>(query);
    const int nblk = (N + BLK_M - 1) / BLK_M;
    gemm_tc<<<nblk, 256, SM_TOTAL>>>(db, N);
    dim3 pgrid(Bq, NPARTS);
    topk_part<<<pgrid, TPB_TOPK>>>(N);
    cand_merge<<<Bq, NPARTS * K_CAND>>>();
    dim3 rgrid(Bq, K_CAND);
    rescore<<<rgrid, 256>>>(db, N);
    topk_final<<<Bq, K_CAND>>>(out, Bq);
    (void)n_in; (void)out_size;
}